// round 15
// baseline (speedup 1.0000x reference)
#include <cuda_runtime.h>
#include <cuda_fp16.h>
#include <cstdint>

#define DINLINE __device__ __forceinline__

static constexpr int MAXN = 2048;
static constexpr int FIN  = 128;

// ---- scratch (device globals; no allocation allowed) ----
__device__ __align__(16) __half g_Ah[5][MAXN][128];   // [sel][n][i] fp16
__device__ __align__(16) __half g_Wh[1152][128];      // [c][k] fp16, N-major
__device__ __align__(16) __half g_Csh[MAXN * 1024];   // spline GEMM out [n][1024], fp16
__device__ unsigned char g_cflp[MAXN * FIN];          // packed [n][q][jp]

// ---------------- PTX helpers ----------------
DINLINE uint32_t smem_u32(const void* p) {
    uint32_t a;
    asm("{ .reg .u64 t; cvta.to.shared.u64 t, %1; cvt.u32.u64 %0, t; }" : "=r"(a) : "l"(p));
    return a;
}
DINLINE void cp16(uint32_t s, const void* g) {
    asm volatile("cp.async.cg.shared.global [%0], [%1], 16;" :: "r"(s), "l"(g));
}
DINLINE void cp_commit() { asm volatile("cp.async.commit_group;"); }
template <int N_> DINLINE void cp_wait() {
    asm volatile("cp.async.wait_group %0;" :: "n"(N_));
}
DINLINE void ldsm_x4(uint32_t& r0, uint32_t& r1, uint32_t& r2, uint32_t& r3, uint32_t addr) {
    asm volatile("ldmatrix.sync.aligned.m8n8.x4.shared.b16 {%0,%1,%2,%3}, [%4];"
                 : "=r"(r0), "=r"(r1), "=r"(r2), "=r"(r3) : "r"(addr));
}
DINLINE void mma16816(float* d, const uint32_t* a, const uint32_t* b) {
    asm volatile(
        "mma.sync.aligned.m16n8k16.row.col.f32.f16.f16.f32 "
        "{%0,%1,%2,%3}, {%4,%5,%6,%7}, {%8,%9}, {%0,%1,%2,%3};"
        : "+f"(d[0]), "+f"(d[1]), "+f"(d[2]), "+f"(d[3])
        : "r"(a[0]), "r"(a[1]), "r"(a[2]), "r"(a[3]), "r"(b[0]), "r"(b[1]));
}
DINLINE uint32_t pack_h2(float a, float b) {
    uint32_t r;
    asm("cvt.rn.f16x2.f32 %0, %1, %2;" : "=r"(r) : "f"(b), "f"(a));
    return r;
}

// ---- K1: all prep. Grid: [0,PA2) act (2 elems/thr); [PA2,PA2+8) baseW; then 128 splineW ----
__global__ void __launch_bounds__(256) k_prep(const float* __restrict__ x,
                                              const float* __restrict__ bw,
                                              const float* __restrict__ sw,
                                              int PA2) {
    __shared__ float tile[32][33];
    const int b = blockIdx.x, t = threadIdx.x;
    if (b < PA2) {
        int idx2 = b * 256 + t;
        int n = idx2 >> 6, c2 = idx2 & 63;
        float2 x0 = *(const float2*)(x + n * 128 + c2 * 2);
        float xv[2] = {x0.x, x0.y};
        float v[5][2];
        uint32_t cfb[2];
        const float s6 = 0.16666666666666666f;
#pragma unroll
        for (int e = 0; e < 2; ++e) {
            float xe = xv[e];
            v[0][e] = xe / (1.0f + __expf(-xe));
            float xn = fminf(fmaxf(xe, -1.0f), 1.0f);
            float tt = (xn + 2.2f) * 2.5f;
            float fl = floorf(tt);
            float u  = tt - fl;
            int ii = (int)fl; ii = ii < 3 ? 3 : (ii > 7 ? 7 : ii);
            float u2 = u * u;
            v[1][e] = s6 * (1.0f + u * (-3.0f + u * (3.0f - u)));
            v[2][e] = s6 * (4.0f + u2 * (3.0f * u - 6.0f));
            v[3][e] = s6 * (1.0f + u * (3.0f + u * (3.0f - 3.0f * u)));
            v[4][e] = s6 * (u2 * u);
            cfb[e] = (uint32_t)(ii - 3);
        }
#pragma unroll
        for (int s = 0; s < 5; ++s)
            *(uint32_t*)&g_Ah[s][n][c2 * 2] = pack_h2(v[s][0], v[s][1]);
        // packed [n][q][jp]: element i -> offset (i&31)*4 + (i>>5)
#pragma unroll
        for (int e = 0; e < 2; ++e) {
            int i = c2 * 2 + e;
            g_cflp[n * 128 + (i & 31) * 4 + (i >> 5)] = (unsigned char)cfb[e];
        }
    } else if (b < PA2 + 8) {
        int f8 = (b - PA2) * 256 + t;
        int c = f8 >> 4, ch = f8 & 15;
        const float4* wp = (const float4*)(bw + c * 128 + ch * 8);
        float4 w0 = wp[0], w1 = wp[1];
        uint4 hv;
        hv.x = pack_h2(w0.x, w0.y);
        hv.y = pack_h2(w0.z, w0.w);
        hv.z = pack_h2(w1.x, w1.y);
        hv.w = pack_h2(w1.z, w1.w);
        *(uint4*)&g_Wh[c][ch * 8] = hv;
    } else {
        int bb = b - PA2 - 8;
        int bc = bb >> 2, bi = bb & 3;
        int tx = t & 31, ty = t >> 5;
#pragma unroll
        for (int iy = 0; iy < 4; ++iy) {
            int il = ty + 8 * iy;
            tile[il][tx] = sw[(bi * 32 + il) * 1024 + bc * 32 + tx];
        }
        __syncthreads();
        {
            int cl = t >> 3, ch = t & 7;
            uint2 hv;
            hv.x = pack_h2(tile[ch * 4 + 0][cl], tile[ch * 4 + 1][cl]);
            hv.y = pack_h2(tile[ch * 4 + 2][cl], tile[ch * 4 + 3][cl]);
            int c = 128 + bc * 32 + cl, i = bi * 32 + ch * 4;
            *(uint2*)&g_Wh[c][i] = hv;
        }
    }
}

// ---- K2: fp16 HMMA GEMM, 512 threads, 4-stage k pipeline. grid (M/128, 9) ----
DINLINE void gemm_pass(uint32_t sb, int ks0, int ks1,
                       int a_lrow, int a_lsel, int b_lrow0, int b_lsel,
                       float (&acc)[2][4][4]) {
#pragma unroll
    for (int ks = ks0; ks < ks1; ++ks) {
        uint32_t af[2][4];
#pragma unroll
        for (int mt = 0; mt < 2; ++mt) {
            int row = a_lrow + mt * 16;
            int q = ks * 2 + a_lsel;
            uint32_t addr = sb + row * 256 + (((q & 8) | ((q ^ row) & 7)) * 16);
            ldsm_x4(af[mt][0], af[mt][1], af[mt][2], af[mt][3], addr);
        }
        uint32_t bf[4][2];
#pragma unroll
        for (int h = 0; h < 2; ++h) {
            int row = b_lrow0 + h * 16;
            int q = ks * 2 + b_lsel;
            uint32_t addr = sb + 32768 + row * 256 + (((q & 8) | ((q ^ row) & 7)) * 16);
            uint32_t r0, r1, r2, r3;
            ldsm_x4(r0, r1, r2, r3, addr);
            bf[h * 2][0] = r0;     bf[h * 2][1] = r1;
            bf[h * 2 + 1][0] = r2; bf[h * 2 + 1][1] = r3;
        }
#pragma unroll
        for (int mt = 0; mt < 2; ++mt)
#pragma unroll
            for (int nt = 0; nt < 4; ++nt)
                mma16816(acc[mt][nt], af[mt], bf[nt]);
    }
}

__global__ void __launch_bounds__(512) k_gemm_mma(float* __restrict__ out) {
    extern __shared__ __align__(128) char smem[];
    const uint32_t sb = smem_u32(smem);
    const int tid = threadIdx.x, lane = tid & 31, wid = tid >> 5;
    const int m0 = blockIdx.x * 128, ct = blockIdx.y;
    const int sel = (ct == 0) ? 0 : 1 + ((ct - 1) >> 1);

    const __half* Asrc = &g_Ah[sel][m0][0];
#pragma unroll
    for (int g = 0; g < 4; ++g) {
        {
            int row = tid >> 2, q = g * 4 + (tid & 3);
            cp16(sb + row * 256 + (((q & 8) | ((q ^ row) & 7)) * 16), Asrc + row * 128 + q * 8);
            cp16(sb + 32768 + row * 256 + (((q & 8) | ((q ^ row) & 7)) * 16),
                 &g_Wh[ct * 128 + row][q * 8]);
        }
        cp_commit();
    }

    const int wm = wid >> 2, wn = wid & 3;
    float acc[2][4][4];
#pragma unroll
    for (int i = 0; i < 2; ++i)
#pragma unroll
        for (int j = 0; j < 4; ++j)
#pragma unroll
            for (int k = 0; k < 4; ++k) acc[i][j][k] = 0.0f;

    const int a_lrow = wm * 32 + (lane & 15);
    const int a_lsel = lane >> 4;
    const int b_lrow0 = wn * 32 + ((lane >> 4) << 3) + (lane & 7);
    const int b_lsel = (lane >> 3) & 1;

    cp_wait<3>();
    __syncthreads();
    gemm_pass(sb, 0, 2, a_lrow, a_lsel, b_lrow0, b_lsel, acc);
    cp_wait<2>();
    __syncthreads();
    gemm_pass(sb, 2, 4, a_lrow, a_lsel, b_lrow0, b_lsel, acc);
    cp_wait<1>();
    __syncthreads();
    gemm_pass(sb, 4, 6, a_lrow, a_lsel, b_lrow0, b_lsel, acc);
    cp_wait<0>();
    __syncthreads();
    gemm_pass(sb, 6, 8, a_lrow, a_lsel, b_lrow0, b_lsel, acc);

    const int er = lane >> 2, ec = (lane & 3) * 2;
    if (ct == 0) {
#pragma unroll
        for (int mt = 0; mt < 2; ++mt)
#pragma unroll
            for (int nt = 0; nt < 4; ++nt) {
                int row = m0 + wm * 32 + mt * 16 + er;
                int col = wn * 32 + nt * 8 + ec;
                *(float2*)&out[row * 128 + col]       = make_float2(acc[mt][nt][0], acc[mt][nt][1]);
                *(float2*)&out[(row + 8) * 128 + col] = make_float2(acc[mt][nt][2], acc[mt][nt][3]);
            }
    } else {
#pragma unroll
        for (int mt = 0; mt < 2; ++mt)
#pragma unroll
            for (int nt = 0; nt < 4; ++nt) {
                int row = m0 + wm * 32 + mt * 16 + er;
                int col = (ct - 1) * 128 + wn * 32 + nt * 8 + ec;
                *(uint32_t*)&g_Csh[row * 1024 + col]       = pack_h2(acc[mt][nt][0], acc[mt][nt][1]);
                *(uint32_t*)&g_Csh[(row + 8) * 1024 + col] = pack_h2(acc[mt][nt][2], acc[mt][nt][3]);
            }
    }
}

// ---- K3: finalize, one thread per (n,q) -> 4 outputs ----
__global__ void __launch_bounds__(256) k_final(float* __restrict__ out) {
    int idx = blockIdx.x * 256 + threadIdx.x;    // (n,q) id
    int n = idx >> 5, q = idx & 31;
    uint32_t cfw = *(const uint32_t*)(g_cflp + n * 128 + q * 4);
    const __half* Cs = g_Csh + n * 1024 + q * 8;
    float4 ov = *(float4*)(out + n * 128 + q * 4);
#pragma unroll
    for (int jp = 0; jp < 4; ++jp) {
        const __half* p = Cs + jp * 256 + ((cfw >> (8 * jp)) & 0xffu);
        ov.x += __half2float(p[0]);
        ov.y += __half2float(p[1]);
        ov.z += __half2float(p[2]);
        ov.w += __half2float(p[3]);
    }
    *(float4*)(out + n * 128 + q * 4) = ov;
}

extern "C" void kernel_launch(void* const* d_in, const int* in_sizes, int n_in,
                              void* d_out, int out_size) {
    const float* x  = (const float*)d_in[0];
    const float* bw = (const float*)d_in[1];
    const float* sw = (const float*)d_in[2];
    float* out = (float*)d_out;
    int N = in_sizes[0] / FIN;
    if (N > MAXN) N = MAXN;

    const int smem = 32768 + 32768;  // 64 KB
    cudaFuncSetAttribute(k_gemm_mma, cudaFuncAttributeMaxDynamicSharedMemorySize, smem);

    int PA2 = (N * FIN) / 512;
    k_prep<<<PA2 + 8 + 128, 256>>>(x, bw, sw, PA2);
    dim3 grid(N / 128, 9);
    k_gemm_mma<<<grid, 512, smem>>>(out);
    k_final<<<(N * 32) / 256, 256>>>(out);
}

// round 16
// speedup vs baseline: 1.0025x; 1.0025x over previous
#include <cuda_runtime.h>
#include <cuda_fp16.h>
#include <cstdint>

#define DINLINE __device__ __forceinline__

static constexpr int MAXN = 2048;
static constexpr int FIN  = 128;

// ---- scratch (device globals; no allocation allowed) ----
__device__ __align__(16) __half g_Ah[5][MAXN][128];   // [sel][n][i] fp16
__device__ __align__(16) __half g_Wh[1152][128];      // [c][k] fp16, N-major
__device__ __align__(16) __half g_Csh[MAXN * 1024];   // spline GEMM out [n][1024], fp16
__device__ unsigned char g_cflp[MAXN * FIN];          // planar [n][jp][q]

// ---------------- PTX helpers ----------------
DINLINE uint32_t smem_u32(const void* p) {
    uint32_t a;
    asm("{ .reg .u64 t; cvta.to.shared.u64 t, %1; cvt.u32.u64 %0, t; }" : "=r"(a) : "l"(p));
    return a;
}
DINLINE void cp16(uint32_t s, const void* g) {
    asm volatile("cp.async.cg.shared.global [%0], [%1], 16;" :: "r"(s), "l"(g));
}
DINLINE void cp_commit() { asm volatile("cp.async.commit_group;"); }
template <int N_> DINLINE void cp_wait() {
    asm volatile("cp.async.wait_group %0;" :: "n"(N_));
}
DINLINE void ldsm_x4(uint32_t& r0, uint32_t& r1, uint32_t& r2, uint32_t& r3, uint32_t addr) {
    asm volatile("ldmatrix.sync.aligned.m8n8.x4.shared.b16 {%0,%1,%2,%3}, [%4];"
                 : "=r"(r0), "=r"(r1), "=r"(r2), "=r"(r3) : "r"(addr));
}
DINLINE void mma16816(float* d, const uint32_t* a, const uint32_t* b) {
    asm volatile(
        "mma.sync.aligned.m16n8k16.row.col.f32.f16.f16.f32 "
        "{%0,%1,%2,%3}, {%4,%5,%6,%7}, {%8,%9}, {%0,%1,%2,%3};"
        : "+f"(d[0]), "+f"(d[1]), "+f"(d[2]), "+f"(d[3])
        : "r"(a[0]), "r"(a[1]), "r"(a[2]), "r"(a[3]), "r"(b[0]), "r"(b[1]));
}
DINLINE uint32_t pack_h2(float a, float b) {
    uint32_t r;
    asm("cvt.rn.f16x2.f32 %0, %1, %2;" : "=r"(r) : "f"(b), "f"(a));
    return r;
}

// ---- K1: all prep. Grid: [0,PA2) act (2 elems/thr); [PA2,PA2+8) baseW; then 128 splineW ----
__global__ void __launch_bounds__(256) k_prep(const float* __restrict__ x,
                                              const float* __restrict__ bw,
                                              const float* __restrict__ sw,
                                              int PA2) {
    __shared__ float tile[32][33];
    const int b = blockIdx.x, t = threadIdx.x;
    if (b < PA2) {
        int idx2 = b * 256 + t;
        int n = idx2 >> 6, c2 = idx2 & 63;
        float2 x0 = *(const float2*)(x + n * 128 + c2 * 2);
        float xv[2] = {x0.x, x0.y};
        float v[5][2];
        uint32_t cfb[2];
        const float s6 = 0.16666666666666666f;
#pragma unroll
        for (int e = 0; e < 2; ++e) {
            float xe = xv[e];
            v[0][e] = __fdividef(xe, 1.0f + __expf(-xe));   // silu via MUFU rcp (was IEEE div)
            float xn = fminf(fmaxf(xe, -1.0f), 1.0f);
            float tt = (xn + 2.2f) * 2.5f;
            float fl = floorf(tt);
            float u  = tt - fl;
            int ii = (int)fl; ii = ii < 3 ? 3 : (ii > 7 ? 7 : ii);
            float u2 = u * u;
            v[1][e] = s6 * (1.0f + u * (-3.0f + u * (3.0f - u)));
            v[2][e] = s6 * (4.0f + u2 * (3.0f * u - 6.0f));
            v[3][e] = s6 * (1.0f + u * (3.0f + u * (3.0f - 3.0f * u)));
            v[4][e] = s6 * (u2 * u);
            cfb[e] = (uint32_t)(ii - 3);
        }
#pragma unroll
        for (int s = 0; s < 5; ++s)
            *(uint32_t*)&g_Ah[s][n][c2 * 2] = pack_h2(v[s][0], v[s][1]);
        // planar [n][jp][q]: i = c2*2 + e; jp = c2>>4, q = (c2&15)*2 + e (consecutive)
        *(unsigned short*)(g_cflp + n * 128 + (c2 >> 4) * 32 + (c2 & 15) * 2) =
            (unsigned short)(cfb[0] | (cfb[1] << 8));
    } else if (b < PA2 + 8) {
        int f8 = (b - PA2) * 256 + t;
        int c = f8 >> 4, ch = f8 & 15;
        const float4* wp = (const float4*)(bw + c * 128 + ch * 8);
        float4 w0 = wp[0], w1 = wp[1];
        uint4 hv;
        hv.x = pack_h2(w0.x, w0.y);
        hv.y = pack_h2(w0.z, w0.w);
        hv.z = pack_h2(w1.x, w1.y);
        hv.w = pack_h2(w1.z, w1.w);
        *(uint4*)&g_Wh[c][ch * 8] = hv;
    } else {
        int bb = b - PA2 - 8;
        int bc = bb >> 2, bi = bb & 3;
        int tx = t & 31, ty = t >> 5;
#pragma unroll
        for (int iy = 0; iy < 4; ++iy) {
            int il = ty + 8 * iy;
            tile[il][tx] = sw[(bi * 32 + il) * 1024 + bc * 32 + tx];
        }
        __syncthreads();
        {
            int cl = t >> 3, ch = t & 7;
            uint2 hv;
            hv.x = pack_h2(tile[ch * 4 + 0][cl], tile[ch * 4 + 1][cl]);
            hv.y = pack_h2(tile[ch * 4 + 2][cl], tile[ch * 4 + 3][cl]);
            int c = 128 + bc * 32 + cl, i = bi * 32 + ch * 4;
            *(uint2*)&g_Wh[c][i] = hv;
        }
    }
}

// ---- K2: fp16 HMMA GEMM, 512 threads (16 warps), 4-stage k pipeline. grid (M/128, 9) ----
DINLINE void gemm_pass(uint32_t sb, int ks0, int ks1,
                       int a_lrow, int a_lsel, int b_lrow0, int b_lsel,
                       float (&acc)[2][4][4]) {
#pragma unroll
    for (int ks = ks0; ks < ks1; ++ks) {
        uint32_t af[2][4];
#pragma unroll
        for (int mt = 0; mt < 2; ++mt) {
            int row = a_lrow + mt * 16;
            int q = ks * 2 + a_lsel;
            uint32_t addr = sb + row * 256 + (((q & 8) | ((q ^ row) & 7)) * 16);
            ldsm_x4(af[mt][0], af[mt][1], af[mt][2], af[mt][3], addr);
        }
        uint32_t bf[4][2];
#pragma unroll
        for (int h = 0; h < 2; ++h) {
            int row = b_lrow0 + h * 16;
            int q = ks * 2 + b_lsel;
            uint32_t addr = sb + 32768 + row * 256 + (((q & 8) | ((q ^ row) & 7)) * 16);
            uint32_t r0, r1, r2, r3;
            ldsm_x4(r0, r1, r2, r3, addr);
            bf[h * 2][0] = r0;     bf[h * 2][1] = r1;
            bf[h * 2 + 1][0] = r2; bf[h * 2 + 1][1] = r3;
        }
#pragma unroll
        for (int mt = 0; mt < 2; ++mt)
#pragma unroll
            for (int nt = 0; nt < 4; ++nt)
                mma16816(acc[mt][nt], af[mt], bf[nt]);
    }
}

__global__ void __launch_bounds__(512) k_gemm_mma(float* __restrict__ out) {
    extern __shared__ __align__(128) char smem[];
    const uint32_t sb = smem_u32(smem);
    const int tid = threadIdx.x, lane = tid & 31, wid = tid >> 5;
    const int m0 = blockIdx.x * 128, ct = blockIdx.y;
    const int sel = (ct == 0) ? 0 : 1 + ((ct - 1) >> 1);

    const __half* Asrc = &g_Ah[sel][m0][0];
#pragma unroll
    for (int g = 0; g < 4; ++g) {
        {
            int row = tid >> 2, q = g * 4 + (tid & 3);
            cp16(sb + row * 256 + (((q & 8) | ((q ^ row) & 7)) * 16), Asrc + row * 128 + q * 8);
            cp16(sb + 32768 + row * 256 + (((q & 8) | ((q ^ row) & 7)) * 16),
                 &g_Wh[ct * 128 + row][q * 8]);
        }
        cp_commit();
    }

    const int wm = wid >> 2, wn = wid & 3;     // warp tile 32x32 (16 warps)
    float acc[2][4][4];
#pragma unroll
    for (int i = 0; i < 2; ++i)
#pragma unroll
        for (int j = 0; j < 4; ++j)
#pragma unroll
            for (int k = 0; k < 4; ++k) acc[i][j][k] = 0.0f;

    const int a_lrow = wm * 32 + (lane & 15);
    const int a_lsel = lane >> 4;
    const int b_lrow0 = wn * 32 + ((lane >> 4) << 3) + (lane & 7);
    const int b_lsel = (lane >> 3) & 1;

    cp_wait<3>();
    __syncthreads();
    gemm_pass(sb, 0, 2, a_lrow, a_lsel, b_lrow0, b_lsel, acc);
    cp_wait<2>();
    __syncthreads();
    gemm_pass(sb, 2, 4, a_lrow, a_lsel, b_lrow0, b_lsel, acc);
    cp_wait<1>();
    __syncthreads();
    gemm_pass(sb, 4, 6, a_lrow, a_lsel, b_lrow0, b_lsel, acc);
    cp_wait<0>();
    __syncthreads();
    gemm_pass(sb, 6, 8, a_lrow, a_lsel, b_lrow0, b_lsel, acc);

    const int er = lane >> 2, ec = (lane & 3) * 2;
    if (ct == 0) {
#pragma unroll
        for (int mt = 0; mt < 2; ++mt)
#pragma unroll
            for (int nt = 0; nt < 4; ++nt) {
                int row = m0 + wm * 32 + mt * 16 + er;
                int col = wn * 32 + nt * 8 + ec;
                *(float2*)&out[row * 128 + col]       = make_float2(acc[mt][nt][0], acc[mt][nt][1]);
                *(float2*)&out[(row + 8) * 128 + col] = make_float2(acc[mt][nt][2], acc[mt][nt][3]);
            }
    } else {
#pragma unroll
        for (int mt = 0; mt < 2; ++mt)
#pragma unroll
            for (int nt = 0; nt < 4; ++nt) {
                int row = m0 + wm * 32 + mt * 16 + er;
                int col = (ct - 1) * 128 + wn * 32 + nt * 8 + ec;
                *(uint32_t*)&g_Csh[row * 1024 + col]       = pack_h2(acc[mt][nt][0], acc[mt][nt][1]);
                *(uint32_t*)&g_Csh[(row + 8) * 1024 + col] = pack_h2(acc[mt][nt][2], acc[mt][nt][3]);
            }
    }
}

// ---- K3: finalize (fp16 gathers, one thread per output) ----
__global__ void __launch_bounds__(256) k_final(float* __restrict__ out) {
    int idx = blockIdx.x * 256 + threadIdx.x;
    int n = idx >> 7, o = idx & 127;
    int q = o >> 2, r2 = o & 3;
    float acc = out[idx];
    const unsigned char* cf = g_cflp + n * 128 + q;
    const __half* Cs = g_Csh + n * 1024 + q * 8 + r2;
    float t0 = __half2float(Cs[cf[0]]);
    float t1 = __half2float(Cs[256 + cf[32]]);
    float t2 = __half2float(Cs[512 + cf[64]]);
    float t3 = __half2float(Cs[768 + cf[96]]);
    out[idx] = acc + (t0 + t1) + (t2 + t3);
}

extern "C" void kernel_launch(void* const* d_in, const int* in_sizes, int n_in,
                              void* d_out, int out_size) {
    const float* x  = (const float*)d_in[0];
    const float* bw = (const float*)d_in[1];
    const float* sw = (const float*)d_in[2];
    float* out = (float*)d_out;
    int N = in_sizes[0] / FIN;
    if (N > MAXN) N = MAXN;

    const int smem = 32768 + 32768;  // 64 KB
    cudaFuncSetAttribute(k_gemm_mma, cudaFuncAttributeMaxDynamicSharedMemorySize, smem);

    int PA2 = (N * FIN) / 512;
    k_prep<<<PA2 + 8 + 128, 256>>>(x, bw, sw, PA2);
    dim3 grid(N / 128, 9);
    k_gemm_mma<<<grid, 512, smem>>>(out);
    k_final<<<(N * FIN) / 256, 256>>>(out);
}